// round 9
// baseline (speedup 1.0000x reference)
#include <cuda_runtime.h>
#include <cstdint>

// Retrace_9844065042706 — affine-segment scan, cp.async smem staging.
// Pass1: block = 4 b x 16 d over a 32-step segment, 64 threads, 42.8KB smem
// -> 5 resident blocks/SM (copy/compute phase diversity). Dense seg-major
// records: g4[s][chain]={A,M,beta,delta}, gal[s][chain]=alpha.
// Pass2: 4 lanes per chain; each lane serially composes 4 segments, then a
// 2-step width-4 shuffle tree composes the 4 partial runs (associative,
// non-commutative compose; lane0 of each group is exact).

#define RB 2048
#define RT 512
#define RD 16
#define SEG 16
#define SEGLEN 32
#define NJ (RT - 1)            // 511
#define BD (RB * RD)           // 32768 chains
#define NBL 4                  // b's per block
#define NTH 64                 // threads (4 b x 16 d)

// smem layout (floats): 5 tensors [4][32][16] (+16 pad per b), then bp [4][33]
#define BSTR  528
#define TS    (NBL * BSTR)     // 2112
#define BPOFF (5 * TS)         // 10560
#define BPSTR 33
#define SMEM_FLOATS (BPOFF + NBL * BPSTR)   // 10692 -> 42768 B
#define SMEM_BYTES  (SMEM_FLOATS * 4)

static constexpr float GAMMA = 0.99f;

// Dense scratch, seg-major (chain-contiguous): 10 MB
__device__ float4 g4 [(size_t)SEG * BD];   // {A, M, beta, delta}
__device__ float  gal[(size_t)SEG * BD];   // alpha

__device__ __forceinline__ void cp16(uint32_t s, const void* g) {
    asm volatile("cp.async.cg.shared.global [%0], [%1], 16;" :: "r"(s), "l"(g));
}
__device__ __forceinline__ void cp4(uint32_t s, const void* g) {
    asm volatile("cp.async.ca.shared.global [%0], [%1], 4;" :: "r"(s), "l"(g));
}
__device__ __forceinline__ void cp_commit() { asm volatile("cp.async.commit_group;"); }
template <int N>
__device__ __forceinline__ void cp_wait() {
    asm volatile("cp.async.wait_group %0;" :: "n"(N));
}
__device__ __forceinline__ uint32_t smem_u32(const void* p) {
    return (uint32_t)__cvta_generic_to_shared(p);
}

// copy rows [k0, k0+16) of the tile (5 tensors + bp)
__device__ __forceinline__ void copy_half(
    float* sm, int tid, int bg, int lo, int k0,
    const float* __restrict__ E, const float* __restrict__ TQ,
    const float* __restrict__ TPP, const float* __restrict__ R,
    const float* __restrict__ Q, const float* __restrict__ BPP)
{
    const uint32_t sbase = smem_u32(sm);
    #pragma unroll 5
    for (int i = tid; i < 1280; i += NTH) {
        const int tensor = i >> 8;
        const int rem    = i & 255;
        const int b      = rem >> 6;
        const int r2     = rem & 63;
        const int k      = k0 + (r2 >> 2);
        const int d4     = r2 & 3;

        const float* gp = (tensor == 0) ? E : (tensor == 1) ? TQ
                        : (tensor == 2) ? TPP : (tensor == 3) ? R : Q;
        const int t = (tensor < 3) ? min(lo + 1 + k, RT - 1) : (lo + k);

        const size_t goff = ((size_t)(bg * NBL + b) * RT + t) * RD + d4 * 4;
        const uint32_t soff = sbase
            + (uint32_t)(tensor * TS + b * BSTR + k * RD + d4 * 4) * 4u;
        cp16(soff, gp + goff);
    }
    {
        const int b = tid >> 4;
        const int k = k0 + (tid & 15);
        const int t = min(lo + 1 + k, RT - 1);
        cp4(sbase + (uint32_t)(BPOFF + b * BPSTR + k) * 4u,
            BPP + (size_t)(bg * NBL + b) * RT + t);
    }
    cp_commit();
}

__global__ void __launch_bounds__(NTH)
retrace_pass1(const float* __restrict__ Q,
              const float* __restrict__ E,
              const float* __restrict__ TQ,
              const float* __restrict__ TPP,
              const float* __restrict__ R,
              const float* __restrict__ BPP,
              float* __restrict__ out)
{
    extern __shared__ float sm[];
    const int tid = threadIdx.x;
    const int s   = blockIdx.x & (SEG - 1);
    const int bg  = blockIdx.x >> 4;           // 0..511

    if (blockIdx.x == 0 && tid == 0) out[0] = 0.0f;

    const int lo    = s * SEGLEN;
    const int steps = min(SEGLEN, NJ - lo);    // 32, or 31 for seg 15

    copy_half(sm, tid, bg, lo, 16, E, TQ, TPP, R, Q, BPP);
    copy_half(sm, tid, bg, lo, 0,  E, TQ, TPP, R, Q, BPP);

    const int b_l = tid >> 4;
    const int d   = tid & 15;
    const int rb  = b_l * BSTR + d;
    const int bpb = BPOFF + b_l * BPSTR;

    float q0 = 0.f, P = 1.f, al = 0.f, be = 0.f, de = 0.f;

    cp_wait<1>();
    __syncthreads();

    #pragma unroll 4
    for (int k = steps - 1; k >= 16; --k) {
        const int ro = rb + k * RD;
        const float e   = sm[ro];
        const float tq  = sm[TS + ro];
        const float tpp = sm[2 * TS + ro];
        const float r   = sm[3 * TS + ro];
        const float qv  = sm[4 * TS + ro];
        const float bp  = sm[bpb + k];

        const float c = __expf(fminf(tpp - bp, 0.f));
        const float m = GAMMA * c;
        const float a = fmaf(GAMMA, fmaf(-c, tq, e), r);
        q0 = fmaf(m, q0, a);  P *= m;
        const float u = qv - q0;
        al = fmaf(u, u, al);  be = fmaf(u, P, be);  de = fmaf(P, P, de);
    }

    cp_wait<0>();
    __syncthreads();

    #pragma unroll 4
    for (int k = 15; k >= 0; --k) {
        const int ro = rb + k * RD;
        const float e   = sm[ro];
        const float tq  = sm[TS + ro];
        const float tpp = sm[2 * TS + ro];
        const float r   = sm[3 * TS + ro];
        const float qv  = sm[4 * TS + ro];
        const float bp  = sm[bpb + k];

        const float c = __expf(fminf(tpp - bp, 0.f));
        const float m = GAMMA * c;
        const float a = fmaf(GAMMA, fmaf(-c, tq, e), r);
        q0 = fmaf(m, q0, a);  P *= m;
        const float u = qv - q0;
        al = fmaf(u, u, al);  be = fmaf(u, P, be);  de = fmaf(P, P, de);
    }

    const int chain = (bg * NBL + b_l) * RD + d;
    const size_t idx = (size_t)s * BD + chain;
    g4 [idx] = make_float4(q0, P, be, de);
    gal[idx] = al;
}

// ---------------------------------------------------------------------------
// Pass 2: 4 lanes per chain (sub = lane&3 handles segs [4sub, 4sub+4)).
// Each lane serially composes its 4 segments high->low, then a 2-step
// width-4 shuffle tree yields the full 16-seg record on sub==0 lanes.
// Compose (X = lower-s run, Y = higher-s run; carry flows Y -> X):
//   al'' = alY + alX - 2 beX AY + deX AY^2
//   be'' = beY + (beX - deX AY) MY
//   de'' = deY + deX MY^2
//   A''  = AX + MX AY ;  M'' = MX MY
// ---------------------------------------------------------------------------
__global__ void __launch_bounds__(128)
retrace_pass2(const float* __restrict__ TQ, float* __restrict__ out)
{
    const int gid   = blockIdx.x * blockDim.x + threadIdx.x;  // 0..4*BD-1
    const int chain = gid >> 2;
    const int sub   = gid & 3;

    // seed with highest segment of this lane's range
    const int shi = sub * 4 + 3;
    size_t idx = (size_t)shi * BD + chain;
    float4 v = g4[idx];
    float A = v.x, M = v.y, be = v.z, de = v.w;
    float al = gal[idx];

    // fold in lower segments (X = new seg, Y = accumulated higher run)
    #pragma unroll
    for (int i = 2; i >= 0; --i) {
        idx = (size_t)(sub * 4 + i) * BD + chain;
        const float4 x = g4[idx];          // AX, MX, beX, deX
        const float alx = gal[idx];

        const float nal = al + alx - 2.0f * x.z * A + x.w * A * A;
        const float nbe = be + (x.z - x.w * A) * M;
        const float nde = de + x.w * M * M;
        const float nA  = fmaf(x.y, A, x.x);
        const float nM  = x.y * M;
        al = nal; be = nbe; de = nde; A = nA; M = nM;
    }

    // 2-step shuffle compose across the 4 sub-lanes (self = X lower, other = Y higher)
    #pragma unroll
    for (int k = 1; k < 4; k <<= 1) {
        const float oA  = __shfl_down_sync(0xffffffffu, A,  k, 4);
        const float oM  = __shfl_down_sync(0xffffffffu, M,  k, 4);
        const float oal = __shfl_down_sync(0xffffffffu, al, k, 4);
        const float obe = __shfl_down_sync(0xffffffffu, be, k, 4);
        const float ode = __shfl_down_sync(0xffffffffu, de, k, 4);

        const float nal = oal + al - 2.0f * be * oA + de * oA * oA;
        const float nbe = obe + (be - de * oA) * oM;
        const float nde = ode + de * oM * oM;
        const float nA  = fmaf(M, oA, A);
        const float nM  = M * oM;
        al = nal; be = nbe; de = nde; A = nA; M = nM;
    }

    float sum = 0.0f;
    if (sub == 0) {
        const int b = chain >> 4;
        const int d = chain & 15;
        const float carry = TQ[((size_t)b * RT + (RT - 1)) * RD + d];
        sum = fmaf(carry, fmaf(de, carry, -2.0f * be), al);
    }

    // block reduce (sum nonzero only on sub==0 lanes)
    #pragma unroll
    for (int o = 16; o > 0; o >>= 1)
        sum += __shfl_down_sync(0xffffffffu, sum, o);

    __shared__ float ws[4];
    const int lane = threadIdx.x & 31;
    const int w    = threadIdx.x >> 5;
    if (lane == 0) ws[w] = sum;
    __syncthreads();

    if (w == 0) {
        float x = (lane < 4) ? ws[lane] : 0.0f;
        #pragma unroll
        for (int o = 2; o > 0; o >>= 1)
            x += __shfl_down_sync(0xffffffffu, x, o);
        if (lane == 0) {
            const float invN = 1.0f / ((float)RB * (float)NJ * (float)RD);
            atomicAdd(out, x * invN);
        }
    }
}

extern "C" void kernel_launch(void* const* d_in, const int* in_sizes, int n_in,
                              void* d_out, int out_size)
{
    const float* Q   = (const float*)d_in[0];
    const float* E   = (const float*)d_in[1];
    const float* TQ  = (const float*)d_in[2];
    const float* R   = (const float*)d_in[3];
    const float* TPP = (const float*)d_in[4];
    const float* BPP = (const float*)d_in[5];
    float* out = (float*)d_out;

    // Pass 1: 512 b-groups x 16 segments = 8192 blocks of 64 threads
    retrace_pass1<<<(RB / NBL) * SEG, NTH, SMEM_BYTES>>>(Q, E, TQ, TPP, R, BPP, out);

    // Pass 2: 4 lanes per chain = 131072 threads
    retrace_pass2<<<(BD * 4) / 128, 128>>>(TQ, out);
}